// round 2
// baseline (speedup 1.0000x reference)
#include <cuda_runtime.h>
#include <cuda_bf16.h>
#include <cstdint>

// Problem constants (fixed by the dataset): input [B, C, T] fp32
#define B_DIM 16
#define C_DIM 256
#define T_DIM 16000
#define TILE_T 256                      // timesteps per block (== blockDim.x)
#define NT ((T_DIM + TILE_T - 1) / TILE_T)   // 63 tiles per batch
#define NTOT (B_DIM * NT)               // 1008 blocks
#define EPS 1e-8f

// ---- scratch for decoupled lookback (device globals: no allocation allowed) ----
__device__ int   g_counter;
__device__ int   g_flag[NTOT];          // 0=invalid, 1=aggregate ready, 2=inclusive ready
__device__ float g_aggS[NTOT], g_aggP[NTOT];
__device__ float g_incS[NTOT], g_incP[NTOT];

__global__ void reset_kernel() {
    int i = blockIdx.x * blockDim.x + threadIdx.x;
    if (i == 0) g_counter = 0;
    if (i < NTOT) g_flag[i] = 0;
}

__global__ __launch_bounds__(TILE_T) void cln_kernel(
    const float* __restrict__ x,
    const float* __restrict__ gain,
    const float* __restrict__ bias,
    float* __restrict__ out)
{
    __shared__ float ssum[TILE_T];
    __shared__ float spow[TILE_T];
    __shared__ float s_gain[C_DIM];
    __shared__ float s_bias[C_DIM];
    __shared__ float s_exc[2];
    __shared__ int   s_ticket;

    const int tid = threadIdx.x;

    // Dynamic tile ticket: atomicAdd order == claim order, so any tile's
    // predecessors in its chain were claimed by blocks that are already
    // running (or finished) -> lookback is deadlock-free.
    if (tid == 0) s_ticket = atomicAdd(&g_counter, 1);
    s_gain[tid] = gain[tid];
    s_bias[tid] = bias[tid];
    __syncthreads();

    const int r    = s_ticket;
    const int b    = r / NT;
    const int tile = r % NT;
    const int t    = tile * TILE_T + tid;
    const bool valid = (t < T_DIM);

    const float* px = x + (size_t)b * C_DIM * T_DIM + t;

    // ---------- Phase 1: per-t reduction over channels (coalesced) ----------
    float s = 0.f, p = 0.f;
    if (valid) {
        #pragma unroll 8
        for (int c = 0; c < C_DIM; c++) {
            float v = px[(size_t)c * T_DIM];
            s += v;
            p = fmaf(v, v, p);
        }
    }

    // ---------- Block-wide inclusive scan over t (Hillis-Steele) ----------
    ssum[tid] = s; spow[tid] = p;
    __syncthreads();
    #pragma unroll
    for (int off = 1; off < TILE_T; off <<= 1) {
        float as = 0.f, ap = 0.f;
        if (tid >= off) { as = ssum[tid - off]; ap = spow[tid - off]; }
        __syncthreads();
        if (tid >= off) { ssum[tid] += as; spow[tid] += ap; }
        __syncthreads();
    }
    const float incS = ssum[tid];
    const float incP = spow[tid];
    const float aggS = ssum[TILE_T - 1];   // invalid tail threads contributed 0
    const float aggP = spow[TILE_T - 1];

    // ---------- Decoupled lookback (thread 0) ----------
    if (tid == 0) {
        const int idx = r;
        const int chain_start = b * NT;    // first tile index of this batch
        volatile int*   vflag = g_flag;
        volatile float* vaS = g_aggS; volatile float* vaP = g_aggP;
        volatile float* viS = g_incS; volatile float* viP = g_incP;

        float excS = 0.f, excP = 0.f;

        if (tile == 0) {
            // Chain start: publish ONLY the inclusive record (flag=2).
            // Never publishes flag=1, so a walker can never step past it.
            viS[idx] = aggS; viP[idx] = aggP;
            __threadfence();
            vflag[idx] = 2;
        } else {
            // Publish aggregate so successors can proceed speculatively.
            vaS[idx] = aggS; vaP[idx] = aggP;
            __threadfence();
            vflag[idx] = 1;

            int pred = idx - 1;
            while (true) {
                int f;
                while ((f = vflag[pred]) == 0) { __nanosleep(40); }
                __threadfence();
                if (f == 2) { excS += viS[pred]; excP += viP[pred]; break; }
                // f == 1: consume aggregate and walk back (never reaches a
                // chain start here, since chain starts only ever publish 2).
                excS += vaS[pred]; excP += vaP[pred];
                pred--;
                if (pred < chain_start) break;   // defensive; unreachable
            }
            viS[idx] = excS + aggS; viP[idx] = excP + aggP;
            __threadfence();
            vflag[idx] = 2;
        }

        s_exc[0] = excS; s_exc[1] = excP;
    }
    __syncthreads();

    // ---------- Phase 2: normalize (tile re-read, mostly L2-resident) ----------
    if (valid) {
        const float cumS = s_exc[0] + incS;
        const float cumP = s_exc[1] + incP;
        const float cnt  = (float)(t + 1) * (float)C_DIM;
        const float mean = cumS / cnt;
        const float var  = cumP / cnt - mean * mean;
        const float inv  = rsqrtf(var + EPS);

        float* po = out + (size_t)b * C_DIM * T_DIM + t;
        #pragma unroll 8
        for (int c = 0; c < C_DIM; c++) {
            float v = px[(size_t)c * T_DIM];
            po[(size_t)c * T_DIM] = fmaf((v - mean) * inv, s_gain[c], s_bias[c]);
        }
    }
}

extern "C" void kernel_launch(void* const* d_in, const int* in_sizes, int n_in,
                              void* d_out, int out_size)
{
    const float* x    = (const float*)d_in[0];
    const float* gain = (const float*)d_in[1];
    const float* bias = (const float*)d_in[2];
    float* out = (float*)d_out;

    reset_kernel<<<(NTOT + 255) / 256, 256>>>();
    cln_kernel<<<NTOT, TILE_T>>>(x, gain, bias, out);
}